// round 15
// baseline (speedup 1.0000x reference)
#include <cuda_runtime.h>

// CTC forward loss. B=32, T=1000, V=1024, L=100, S=2L+1=201.
//
// Pass 1: g_emit[b][t][s] = pred[b][t][ext[s]] + EPS (linear; 0 if invalid),
//   rows of 256 floats.
// Pass 2: SINGLE-WARP DP, 8 lanes/thread in registers a0..a7.
//   Only cross-thread value per step: neighbor's a7 via ONE shfl_up.
//   No __syncthreads, no smem in the loop. Exact 2^k rescale every 4 steps
//   via __reduce_max_sync (target 2^120), IEEE ops. Mean-reduce fused.

#define Bc 32
#define Tc 1000
#define Vc 1024
#define Lc 100
#define Sc 201
#define EPSV (1e-7f)
#define EMIT_NT 256
#define ESTR 256            // emission row stride in floats
#define LN2F 0.6931471805599453f

__device__ float    g_emit[(size_t)Bc * Tc * ESTR];   // ~32.8 MB scratch
__device__ float    g_loss[Bc];
__device__ unsigned g_done;                           // zero-init; atomicInc wraps

__device__ __forceinline__ float lg2f_(float x) { float y; asm("lg2.approx.ftz.f32 %0, %1;" : "=f"(y) : "f"(x)); return y; }

// ---------------- Pass 1: emission gather (parallel, linear) ----------------
__global__ __launch_bounds__(EMIT_NT)
void ctc_emit_kernel(const float* __restrict__ pred,
                     const int*   __restrict__ lenA,
                     const int*   __restrict__ lenB,
                     const int*   __restrict__ labels)
{
    const int t = blockIdx.x;
    const int b = blockIdx.y;
    const int s = threadIdx.x;

    const int la = lenA[b], lb = lenB[b];
    const int ilen = min(max(max(la, lb), 1), Tc);
    const int llen = min(max(min(la, lb), 1), Lc);
    if (t >= ilen) return;

    int ext = Vc - 1;
    if ((s & 1) && s < Sc) ext = labels[b * Lc + (s >> 1)] & (Vc - 1);

    const bool valid = (s < Sc) && (s < 2 * llen + 1);
    const float p = pred[((size_t)b * Tc + t) * Vc + ext];
    g_emit[((size_t)b * Tc + t) * ESTR + s] = valid ? (p + EPSV) : 0.0f;
}

// skip coefficient for extended lane x
__device__ __forceinline__ float allow_at(int x, const int* lab, int b)
{
    if (x < 1 || x >= Sc || !(x & 1)) return 0.0f;
    if (x == 1) return 1.0f;
    const int e0 = lab[b * Lc + (x >> 1)]     & (Vc - 1);
    const int e1 = lab[b * Lc + (x >> 1) - 1] & (Vc - 1);
    return (e0 != e1) ? 1.0f : 0.0f;
}

// one DP step over this thread's 8 lanes (in place, descending order).
// n = alpha[8j-1] (neighbor's old a7). e = 8 emissions for this step.
#define STEP_BODY(E0,E1,E2,E3,E4,E5,E6,E7)                                        \
    {                                                                             \
        float n = __shfl_up_sync(0xffffffffu, a7, 1);                             \
        if (lane == 0) n = 0.0f;                                                  \
        a7 = __fmul_rn(__fmaf_rn(al7, a5, __fadd_rn(a7, a6)), (E7));              \
        a6 = __fmul_rn(__fadd_rn(a6, a5), (E6));                                  \
        a5 = __fmul_rn(__fmaf_rn(al5, a3, __fadd_rn(a5, a4)), (E5));              \
        a4 = __fmul_rn(__fadd_rn(a4, a3), (E4));                                  \
        a3 = __fmul_rn(__fmaf_rn(al3, a1, __fadd_rn(a3, a2)), (E3));              \
        a2 = __fmul_rn(__fadd_rn(a2, a1), (E2));                                  \
        a1 = __fmul_rn(__fmaf_rn(al1, n,  __fadd_rn(a1, a0)), (E1));              \
        a0 = __fmul_rn(__fadd_rn(a0, n),  (E0));                                  \
    }

#define APPLY_PEND()                                                              \
    {                                                                             \
        a0 = __fmul_rn(__fmul_rn(a0, pend1), pend2);                              \
        a1 = __fmul_rn(__fmul_rn(a1, pend1), pend2);                              \
        a2 = __fmul_rn(__fmul_rn(a2, pend1), pend2);                              \
        a3 = __fmul_rn(__fmul_rn(a3, pend1), pend2);                              \
        a4 = __fmul_rn(__fmul_rn(a4, pend1), pend2);                              \
        a5 = __fmul_rn(__fmul_rn(a5, pend1), pend2);                              \
        a6 = __fmul_rn(__fmul_rn(a6, pend1), pend2);                              \
        a7 = __fmul_rn(__fmul_rn(a7, pend1), pend2);                              \
        Ktot += kPend;                                                            \
    }

#define MEASURE_PEND()                                                            \
    {                                                                             \
        float mm = fmaxf(fmaxf(fmaxf(a0, a1), fmaxf(a2, a3)),                     \
                         fmaxf(fmaxf(a4, a5), fmaxf(a6, a7)));                    \
        const unsigned M = __reduce_max_sync(0xffffffffu, __float_as_uint(mm));   \
        const int ee = (int)((M >> 23) & 0xFFu);                                  \
        kPend = 247 - ee;                      /* rescale target 2^120 */         \
        const int k1 = kPend >> 1;                                                \
        pend1 = __uint_as_float((unsigned)(127 + k1) << 23);                      \
        pend2 = __uint_as_float((unsigned)(127 + (kPend - k1)) << 23);            \
    }

// ---------------- Pass 2: single-warp DP ----------------
__global__ __launch_bounds__(32, 1)
void ctc_dp_kernel(const int* __restrict__ lenA,
                   const int* __restrict__ lenB,
                   const int* __restrict__ labels,
                   float*     __restrict__ out)
{
    __shared__ float afin[ESTR];

    const int b    = blockIdx.x;
    const int lane = threadIdx.x;        // owns lanes 8*lane .. 8*lane+7
    const int s0   = 8 * lane;

    const int la = lenA[b], lb = lenB[b];
    const int ilen = min(max(max(la, lb), 1), Tc);
    const int llen = min(max(min(la, lb), 1), Lc);

    // skip coefficients: only odd slots (fixed parity since 8 is even)
    const float al1 = allow_at(s0 + 1, labels, b);
    const float al3 = allow_at(s0 + 3, labels, b);
    const float al5 = allow_at(s0 + 5, labels, b);
    const float al7 = allow_at(s0 + 7, labels, b);

    const float4* eb = (const float4*)(g_emit + (size_t)b * Tc * ESTR) + 2 * lane;

    // ---- t = 0 (emit already zeroed invalid lanes; lanes 0,1 live in thread 0)
    float a0 = 0.f, a1 = 0.f, a2 = 0.f, a3 = 0.f, a4 = 0.f, a5 = 0.f, a6 = 0.f, a7 = 0.f;
    if (lane == 0) { const float4 e = eb[0]; a0 = e.x; a1 = e.y; }

    // ---- preload emissions for steps t = 1..8 (8-deep, constant-indexed) ----
    float4 eL0, eH0, eL1, eH1, eL2, eH2, eL3, eH3, eL4, eH4, eL5, eH5, eL6, eH6, eL7, eH7;
    {
        #define LD(i, VL, VH) { const int tn = min(1 + (i), Tc - 1);              \
            VL = eb[(size_t)tn * (ESTR/4)]; VH = eb[(size_t)tn * (ESTR/4) + 1]; }
        LD(0, eL0, eH0) LD(1, eL1, eH1) LD(2, eL2, eH2) LD(3, eL3, eH3)
        LD(4, eL4, eH4) LD(5, eL5, eH5) LD(6, eL6, eH6) LD(7, eL7, eH7)
        #undef LD
    }

    int   t = 1, Ktot = 0, kPend = 0;
    float pend1 = 1.0f, pend2 = 1.0f;    // neutral first application (exact)

    // ---- main loop: 8 steps per iteration, no barriers ----
    while (t + 8 <= ilen) {
        #define DOSTEP(i, VL, VH, APPLY, MEASURE)                                 \
        {                                                                         \
            if (APPLY) APPLY_PEND();                                              \
            STEP_BODY(VL.x, VL.y, VL.z, VL.w, VH.x, VH.y, VH.z, VH.w);            \
            if (MEASURE) MEASURE_PEND();                                          \
            const int tn = min(t + 8 + (i), Tc - 1);                              \
            VL = eb[(size_t)tn * (ESTR/4)];                                       \
            VH = eb[(size_t)tn * (ESTR/4) + 1];                                   \
        }
        DOSTEP(0, eL0, eH0, 1, 0)
        DOSTEP(1, eL1, eH1, 0, 0)
        DOSTEP(2, eL2, eH2, 0, 0)
        DOSTEP(3, eL3, eH3, 0, 1)
        DOSTEP(4, eL4, eH4, 1, 0)
        DOSTEP(5, eL5, eH5, 0, 0)
        DOSTEP(6, eL6, eH6, 0, 0)
        DOSTEP(7, eL7, eH7, 0, 1)
        #undef DOSTEP
        t += 8;
    }

    // ---- tail (< 8 steps); emissions already resident ----
    {
        int rem = ilen - t;
        #define TAILSTEP(i, VL, VH)                                               \
            if (rem > (i)) {                                                      \
                if ((i) == 0) APPLY_PEND();                                       \
                STEP_BODY(VL.x, VL.y, VL.z, VL.w, VH.x, VH.y, VH.z, VH.w);        \
            }
        TAILSTEP(0, eL0, eH0)
        TAILSTEP(1, eL1, eH1)
        TAILSTEP(2, eL2, eH2)
        TAILSTEP(3, eL3, eH3)
        TAILSTEP(4, eL4, eH4)
        TAILSTEP(5, eL5, eH5)
        TAILSTEP(6, eL6, eH6)
        #undef TAILSTEP
        // (empty tail: pending rescale never applied & never counted -- consistent)
    }

    // ---- finalize: dump lanes, loglik, fused mean ----
    afin[s0 + 0] = a0; afin[s0 + 1] = a1; afin[s0 + 2] = a2; afin[s0 + 3] = a3;
    afin[s0 + 4] = a4; afin[s0 + 5] = a5; afin[s0 + 6] = a6; afin[s0 + 7] = a7;
    __syncwarp();
    if (lane == 0) {
        const float a1f = afin[2 * llen - 1];
        const float a2f = afin[2 * llen];
        const float ll  = (lg2f_(__fadd_rn(a1f, a2f)) - (float)Ktot) * LN2F;
        g_loss[b] = -ll;

        __threadfence();
        const unsigned old = atomicInc(&g_done, Bc - 1);
        if (old == Bc - 1) {
            __threadfence();
            float acc = 0.0f;
            #pragma unroll
            for (int i = 0; i < Bc; ++i) acc += g_loss[i];
            out[0] = acc * (1.0f / (float)Bc);
        }
    }
}

extern "C" void kernel_launch(void* const* d_in, const int* in_sizes, int n_in,
                              void* d_out, int out_size)
{
    // Identify inputs by size rank (robust to ordering / bytes-vs-elems).
    int idx[4] = {0, 1, 2, 3};
    for (int i = 0; i < 3; ++i)
        for (int j = i + 1; j < 4; ++j)
            if ((long long)in_sizes[idx[j]] > (long long)in_sizes[idx[i]]) {
                int tmp = idx[i]; idx[i] = idx[j]; idx[j] = tmp;
            }

    const float* pred   = (const float*)d_in[idx[0]];  // [B,T,V]
    const int*   labels = (const int*)  d_in[idx[1]];  // [B,L]
    const int*   lenA   = (const int*)  d_in[idx[2]];  // length vectors
    const int*   lenB   = (const int*)  d_in[idx[3]];

    float* out = (float*)d_out;

    dim3 g1(Tc, Bc);
    ctc_emit_kernel<<<g1, EMIT_NT>>>(pred, lenA, lenB, labels);
    ctc_dp_kernel<<<Bc, 32>>>(lenA, lenB, labels, out);
}

// round 17
// speedup vs baseline: 1.1673x; 1.1673x over previous
#include <cuda_runtime.h>

// CTC forward loss. B=32, T=1000, V=1024, L=100, S=2L+1=201.
//
// Pass 1: g_emit[b][t][s] = pred[b][t][ext[s]] + EPS (linear; 0 if invalid),
//   rows of 256 floats, padded to 1024 rows per batch (prefetch overrun-safe).
// Pass 2: SINGLE-WARP DP (R15, passed @1.64e-4), 8 lanes/thread in registers,
//   8-deep register emission prefetch. R17 deltas vs R15:
//     - immediate-offset LDGs via one per-iteration pointer (no min clamps,
//       no 64-bit muls per load)  -> fewer issued instructions/step
//     - prefetch.global.L2 at 16-step lookahead -> DRAM latency hidden with
//       zero register/tracking cost
//   One shfl/step, no barriers; exact 2^k rescale every 4 steps (target 2^120),
//   IEEE ops. Mean-reduce fused.

#define Bc 32
#define Tc 1000
#define TPAD 1024             // padded rows per batch (prefetch overrun-safe)
#define Vc 1024
#define Lc 100
#define Sc 201
#define EPSV (1e-7f)
#define EMIT_NT 256
#define ESTR 256              // emission row stride in floats (1024 B)
#define LN2F 0.6931471805599453f

__device__ float    g_emit[(size_t)Bc * TPAD * ESTR];  // ~33.6 MB scratch
__device__ float    g_loss[Bc];
__device__ unsigned g_done;                            // zero-init; atomicInc wraps

__device__ __forceinline__ float lg2f_(float x) { float y; asm("lg2.approx.ftz.f32 %0, %1;" : "=f"(y) : "f"(x)); return y; }

#define PF_L2(P) asm volatile("prefetch.global.L2 [%0];" :: "l"(P))

// ---------------- Pass 1: emission gather (parallel, linear) ----------------
__global__ __launch_bounds__(EMIT_NT)
void ctc_emit_kernel(const float* __restrict__ pred,
                     const int*   __restrict__ lenA,
                     const int*   __restrict__ lenB,
                     const int*   __restrict__ labels)
{
    const int t = blockIdx.x;
    const int b = blockIdx.y;
    const int s = threadIdx.x;

    const int la = lenA[b], lb = lenB[b];
    const int ilen = min(max(max(la, lb), 1), Tc);
    const int llen = min(max(min(la, lb), 1), Lc);
    if (t >= ilen) return;

    int ext = Vc - 1;
    if ((s & 1) && s < Sc) ext = labels[b * Lc + (s >> 1)] & (Vc - 1);

    const bool valid = (s < Sc) && (s < 2 * llen + 1);
    const float p = pred[((size_t)b * Tc + t) * Vc + ext];
    g_emit[((size_t)b * TPAD + t) * ESTR + s] = valid ? (p + EPSV) : 0.0f;
}

// skip coefficient for extended lane x
__device__ __forceinline__ float allow_at(int x, const int* lab, int b)
{
    if (x < 1 || x >= Sc || !(x & 1)) return 0.0f;
    if (x == 1) return 1.0f;
    const int e0 = lab[b * Lc + (x >> 1)]     & (Vc - 1);
    const int e1 = lab[b * Lc + (x >> 1) - 1] & (Vc - 1);
    return (e0 != e1) ? 1.0f : 0.0f;
}

// one DP step over this thread's 8 lanes (in place, descending order)
#define STEP_BODY(E0,E1,E2,E3,E4,E5,E6,E7)                                        \
    {                                                                             \
        float n = __shfl_up_sync(0xffffffffu, a7, 1);                             \
        if (lane == 0) n = 0.0f;                                                  \
        a7 = __fmul_rn(__fmaf_rn(al7, a5, __fadd_rn(a7, a6)), (E7));              \
        a6 = __fmul_rn(__fadd_rn(a6, a5), (E6));                                  \
        a5 = __fmul_rn(__fmaf_rn(al5, a3, __fadd_rn(a5, a4)), (E5));              \
        a4 = __fmul_rn(__fadd_rn(a4, a3), (E4));                                  \
        a3 = __fmul_rn(__fmaf_rn(al3, a1, __fadd_rn(a3, a2)), (E3));              \
        a2 = __fmul_rn(__fadd_rn(a2, a1), (E2));                                  \
        a1 = __fmul_rn(__fmaf_rn(al1, n,  __fadd_rn(a1, a0)), (E1));              \
        a0 = __fmul_rn(__fadd_rn(a0, n),  (E0));                                  \
    }

#define APPLY_PEND()                                                              \
    {                                                                             \
        a0 = __fmul_rn(__fmul_rn(a0, pend1), pend2);                              \
        a1 = __fmul_rn(__fmul_rn(a1, pend1), pend2);                              \
        a2 = __fmul_rn(__fmul_rn(a2, pend1), pend2);                              \
        a3 = __fmul_rn(__fmul_rn(a3, pend1), pend2);                              \
        a4 = __fmul_rn(__fmul_rn(a4, pend1), pend2);                              \
        a5 = __fmul_rn(__fmul_rn(a5, pend1), pend2);                              \
        a6 = __fmul_rn(__fmul_rn(a6, pend1), pend2);                              \
        a7 = __fmul_rn(__fmul_rn(a7, pend1), pend2);                              \
        Ktot += kPend;                                                            \
    }

#define MEASURE_PEND()                                                            \
    {                                                                             \
        float mm = fmaxf(fmaxf(fmaxf(a0, a1), fmaxf(a2, a3)),                     \
                         fmaxf(fmaxf(a4, a5), fmaxf(a6, a7)));                    \
        const unsigned M = __reduce_max_sync(0xffffffffu, __float_as_uint(mm));   \
        const int ee = (int)((M >> 23) & 0xFFu);                                  \
        kPend = 247 - ee;                      /* rescale target 2^120 */         \
        const int k1 = kPend >> 1;                                                \
        pend1 = __uint_as_float((unsigned)(127 + k1) << 23);                      \
        pend2 = __uint_as_float((unsigned)(127 + (kPend - k1)) << 23);            \
    }

// ---------------- Pass 2: single-warp DP ----------------
__global__ __launch_bounds__(32, 1)
void ctc_dp_kernel(const int* __restrict__ lenA,
                   const int* __restrict__ lenB,
                   const int* __restrict__ labels,
                   float*     __restrict__ out)
{
    __shared__ float afin[ESTR];

    const int b    = blockIdx.x;
    const int lane = threadIdx.x;        // owns lanes 8*lane .. 8*lane+7
    const int s0   = 8 * lane;

    const int la = lenA[b], lb = lenB[b];
    const int ilen = min(max(max(la, lb), 1), Tc);
    const int llen = min(max(min(la, lb), 1), Lc);

    const float al1 = allow_at(s0 + 1, labels, b);
    const float al3 = allow_at(s0 + 3, labels, b);
    const float al5 = allow_at(s0 + 5, labels, b);
    const float al7 = allow_at(s0 + 7, labels, b);

    // per-thread float4-pair base: row r at eb[r*64], eb[r*64+1]
    const float4* eb = (const float4*)(g_emit + (size_t)b * TPAD * ESTR) + 2 * lane;

    // ---- t = 0 (emit already zeroed invalid lanes; lanes 0,1 in thread 0)
    float a0 = 0.f, a1 = 0.f, a2 = 0.f, a3 = 0.f, a4 = 0.f, a5 = 0.f, a6 = 0.f, a7 = 0.f;
    if (lane == 0) { const float4 e = eb[0]; a0 = e.x; a1 = e.y; }

    // ---- preload emissions for steps 1..8 (ilen >= 500: all valid) ----
    float4 eL0, eH0, eL1, eH1, eL2, eH2, eL3, eH3, eL4, eH4, eL5, eH5, eL6, eH6, eL7, eH7;
    eL0 = eb[1 * 64]; eH0 = eb[1 * 64 + 1];
    eL1 = eb[2 * 64]; eH1 = eb[2 * 64 + 1];
    eL2 = eb[3 * 64]; eH2 = eb[3 * 64 + 1];
    eL3 = eb[4 * 64]; eH3 = eb[4 * 64 + 1];
    eL4 = eb[5 * 64]; eH4 = eb[5 * 64 + 1];
    eL5 = eb[6 * 64]; eH5 = eb[6 * 64 + 1];
    eL6 = eb[7 * 64]; eH6 = eb[7 * 64 + 1];
    eL7 = eb[8 * 64]; eH7 = eb[8 * 64 + 1];

    // warm L2 for steps 9..24
    {
        const char* p0 = (const char*)(eb + (size_t)9 * 64);
        #pragma unroll
        for (int i = 0; i < 16; ++i) { PF_L2(p0 + i * 1024); PF_L2(p0 + i * 1024 + 512); }
    }

    int   t = 1, Ktot = 0, kPend = 0;
    float pend1 = 1.0f, pend2 = 1.0f;    // neutral first application (exact)

    // ---- main loop: 8 steps per iteration, no barriers ----
    while (t + 8 <= ilen) {
        const float4* ep = eb + (size_t)(t + 8) * 64;           // loads: steps t+8..t+15
        const char*   pq = (const char*)(eb + (size_t)(t + 16) * 64);  // L2 prefetch: t+16..t+23

        #define DOSTEP(I, VL, VH, APPLY, MEASURE)                                 \
        {                                                                         \
            if (APPLY) APPLY_PEND();                                              \
            STEP_BODY(VL.x, VL.y, VL.z, VL.w, VH.x, VH.y, VH.z, VH.w);            \
            if (MEASURE) MEASURE_PEND();                                          \
            PF_L2(pq + (I) * 1024);                                               \
            PF_L2(pq + (I) * 1024 + 512);                                         \
            VL = ep[(I) * 64];                                                    \
            VH = ep[(I) * 64 + 1];                                                \
        }
        DOSTEP(0, eL0, eH0, 1, 0)
        DOSTEP(1, eL1, eH1, 0, 0)
        DOSTEP(2, eL2, eH2, 0, 0)
        DOSTEP(3, eL3, eH3, 0, 1)
        DOSTEP(4, eL4, eH4, 1, 0)
        DOSTEP(5, eL5, eH5, 0, 0)
        DOSTEP(6, eL6, eH6, 0, 0)
        DOSTEP(7, eL7, eH7, 0, 1)
        #undef DOSTEP
        t += 8;
    }

    // ---- tail (< 8 steps); emissions already resident ----
    {
        const int rem = ilen - t;
        #define TAILSTEP(I, VL, VH)                                               \
            if (rem > (I)) {                                                      \
                if ((I) == 0) APPLY_PEND();                                       \
                STEP_BODY(VL.x, VL.y, VL.z, VL.w, VH.x, VH.y, VH.z, VH.w);        \
            }
        TAILSTEP(0, eL0, eH0)
        TAILSTEP(1, eL1, eH1)
        TAILSTEP(2, eL2, eH2)
        TAILSTEP(3, eL3, eH3)
        TAILSTEP(4, eL4, eH4)
        TAILSTEP(5, eL5, eH5)
        TAILSTEP(6, eL6, eH6)
        #undef TAILSTEP
        // (empty tail: pending rescale never applied & never counted -- consistent)
    }

    // ---- finalize: dump lanes, loglik, fused mean ----
    afin[s0 + 0] = a0; afin[s0 + 1] = a1; afin[s0 + 2] = a2; afin[s0 + 3] = a3;
    afin[s0 + 4] = a4; afin[s0 + 5] = a5; afin[s0 + 6] = a6; afin[s0 + 7] = a7;
    __syncwarp();
    if (lane == 0) {
        const float a1f = afin[2 * llen - 1];
        const float a2f = afin[2 * llen];
        const float ll  = (lg2f_(__fadd_rn(a1f, a2f)) - (float)Ktot) * LN2F;
        g_loss[b] = -ll;

        __threadfence();
        const unsigned old = atomicInc(&g_done, Bc - 1);
        if (old == Bc - 1) {
            __threadfence();
            float acc = 0.0f;
            #pragma unroll
            for (int i = 0; i < Bc; ++i) acc += g_loss[i];
            out[0] = acc * (1.0f / (float)Bc);
        }
    }
}

extern "C" void kernel_launch(void* const* d_in, const int* in_sizes, int n_in,
                              void* d_out, int out_size)
{
    // Identify inputs by size rank (robust to ordering / bytes-vs-elems).
    int idx[4] = {0, 1, 2, 3};
    for (int i = 0; i < 3; ++i)
        for (int j = i + 1; j < 4; ++j)
            if ((long long)in_sizes[idx[j]] > (long long)in_sizes[idx[i]]) {
                int tmp = idx[i]; idx[i] = idx[j]; idx[j] = tmp;
            }

    const float* pred   = (const float*)d_in[idx[0]];  // [B,T,V]
    const int*   labels = (const int*)  d_in[idx[1]];  // [B,L]
    const int*   lenA   = (const int*)  d_in[idx[2]];  // length vectors
    const int*   lenB   = (const int*)  d_in[idx[3]];

    float* out = (float*)d_out;

    dim3 g1(Tc, Bc);
    ctc_emit_kernel<<<g1, EMIT_NT>>>(pred, lenA, lenB, labels);
    ctc_dp_kernel<<<Bc, 32>>>(lenA, lenB, labels, out);
}